// round 4
// baseline (speedup 1.0000x reference)
#include <cuda_runtime.h>
#include <math.h>

#define MAX_T (64 * 4096)
#define MAX_B 64
#define MAX_K 1024
#define SPLIT 16          // gather work items per graph
#define TILE_ROWS 32      // rows per dot ticket (one pass of 8 warps x 4 rows)

// ---------------- device scratch (no allocs allowed) ----------------
__device__ float g_dot[MAX_T];
__device__ int   g_idx[MAX_B * MAX_K];
__device__ int   g_tileTicket;
__device__ int   g_gatherTicket;
__device__ int   g_doneTiles[MAX_B];
__device__ int   g_flag[MAX_B];      // 1 = graph's idx list + zeroed output row ready
__device__ int   g_frontier;         // graphs [0, frontier) all ready (monotonic)

__global__ void init_kernel() {
    int i = threadIdx.x;
    if (i == 0) { g_tileTicket = 0; g_gatherTicket = 0; g_frontier = 0; }
    if (i < MAX_B) { g_doneTiles[i] = 0; g_flag[i] = 0; }
}

// ---------------- shared memory layout ----------------
struct SMem {
    float4   proj[64];        // projection vector (D=256 floats)
    unsigned keys[4096];      // radix-select keys for one graph
    unsigned hist[256];
    unsigned sfx[256];
    unsigned s_chosen, s_need;
    int      cntGT, cntEQ;
    int      s_ticket;
    int      s_flagdone;
    int      sidx[80];        // staged gather indices for one slice
};

// ---------------- inline per-graph radix select (256 threads) ----------------
__device__ void select_graph(int b, int N, int K, int D,
                             float* __restrict__ out, SMem& sm) {
    const int TB = 256;
    int tid = threadIdx.x;

    // zero this graph's output row before publishing readiness
    for (int i = tid; i < D; i += TB) out[(size_t)b * D + i] = 0.0f;

    for (int i = tid; i < N; i += TB) {
        unsigned u = __float_as_uint(__ldcg(&g_dot[(size_t)b * N + i]));
        u ^= (u >> 31) ? 0xFFFFFFFFu : 0x80000000u;   // order-preserving
        sm.keys[i] = u;
    }
    if (tid == 0) sm.s_need = (unsigned)K;
    __syncthreads();

    unsigned prefix = 0, mask = 0;
#pragma unroll
    for (int pass = 0; pass < 4; pass++) {
        int shift = 24 - 8 * pass;
        unsigned need = sm.s_need;
        sm.hist[tid] = 0;
        __syncthreads();
        for (int i = tid; i < N; i += TB) {
            unsigned kk = sm.keys[i];
            if ((kk & mask) == prefix)
                atomicAdd(&sm.hist[(kk >> shift) & 0xFFu], 1u);
        }
        __syncthreads();
        sm.sfx[tid] = sm.hist[tid];
        __syncthreads();
#pragma unroll
        for (int off = 1; off < 256; off <<= 1) {
            unsigned v = (tid + off < 256) ? sm.sfx[tid + off] : 0u;
            __syncthreads();
            sm.sfx[tid] += v;
            __syncthreads();
        }
        {
            unsigned st = sm.sfx[tid];
            unsigned sn = (tid < 255) ? sm.sfx[tid + 1] : 0u;
            if (st >= need && sn < need) {   // largest bin with suffix >= need
                sm.s_chosen = (unsigned)tid;
                sm.s_need = need - sn;
            }
        }
        __syncthreads();
        prefix |= sm.s_chosen << shift;
        mask   |= 0xFFu << shift;
        __syncthreads();
    }

    unsigned thr = prefix;  // exact key of the k-th largest
    if (tid == 0) {
        sm.cntGT = 0;
        sm.cntEQ = K - (int)sm.s_need;   // ties fill [cntGT_final, K)
    }
    __syncthreads();

    int* lst = g_idx + (size_t)b * K;
    for (int i = tid; i < N; i += TB) {
        unsigned kk = sm.keys[i];
        if (kk > thr) {
            int p = atomicAdd(&sm.cntGT, 1);
            lst[p] = b * N + i;
        } else if (kk == thr) {
            int p = atomicAdd(&sm.cntEQ, 1);
            if (p < K) lst[p] = b * N + i;
        }
    }
    __syncthreads();
}

// ---------------- gather one work item (graph b, slice s) ----------------
__device__ void gather_item(int b, int s, int K, int D,
                            const float* __restrict__ logits,
                            float* __restrict__ out, SMem& sm) {
    const int TB = 256;
    int tid = threadIdx.x;
    int per = (K + SPLIT - 1) / SPLIT;
    int r0 = s * per;
    int cnt = min(K, r0 + per) - r0;
    if (cnt <= 0) return;

    if (tid < cnt) sm.sidx[tid] = __ldcg(&g_idx[(size_t)b * K + r0 + tid]);
    __syncthreads();

    for (int col = tid; col < D; col += TB) {
        float acc = 0.0f;
        int r = 0;
#pragma unroll 1
        for (; r + 8 <= cnt; r += 8) {
            float v0 = logits[(size_t)sm.sidx[r + 0] * D + col];
            float v1 = logits[(size_t)sm.sidx[r + 1] * D + col];
            float v2 = logits[(size_t)sm.sidx[r + 2] * D + col];
            float v3 = logits[(size_t)sm.sidx[r + 3] * D + col];
            float v4 = logits[(size_t)sm.sidx[r + 4] * D + col];
            float v5 = logits[(size_t)sm.sidx[r + 5] * D + col];
            float v6 = logits[(size_t)sm.sidx[r + 6] * D + col];
            float v7 = logits[(size_t)sm.sidx[r + 7] * D + col];
            acc += ((v0 + v1) + (v2 + v3)) + ((v4 + v5) + (v6 + v7));
        }
        for (; r < cnt; r++) acc += logits[(size_t)sm.sidx[r] * D + col];
        atomicAdd(&out[(size_t)b * D + col], acc);
    }
    __syncthreads();   // protect sm.sidx before reuse
}

// ---------------- fused persistent kernel ----------------
__global__ void __launch_bounds__(256)
fused_kernel(const float* __restrict__ logits,
             const float* __restrict__ proj,
             float* __restrict__ out,
             int T, int N, int K, int D, int B) {
    __shared__ SMem sm;
    int tid = threadIdx.x;
    int wid = tid >> 5, lane = tid & 31;

    if (tid < 64) sm.proj[tid] = reinterpret_cast<const float4*>(proj)[tid];
    __syncthreads();

    const int totalTiles = T / TILE_ROWS;
    const int tilesPerGraph = N / TILE_ROWS;
    const int totalGatherTickets = B * SPLIT;

    float4 pa = sm.proj[lane];
    float4 pc = sm.proj[lane + 32];

    // ---------- phase 1: dot tiles (graph-ordered) + inline select +
    //                     opportunistic bounded gather ----------
    while (true) {
        if (tid == 0) sm.s_ticket = atomicAdd(&g_tileTicket, 1);
        __syncthreads();
        int t = sm.s_ticket;
        __syncthreads();
        if (t >= totalTiles) break;

        // compute 32 rows of dots: warp wid handles rows base + wid*4 .. +3
        int base = t * TILE_ROWS;
        int row0 = base + wid * 4;
        {
            const float4* rp = reinterpret_cast<const float4*>(logits) + (size_t)row0 * 64;
            float4 a[4], c[4];
#pragma unroll
            for (int r = 0; r < 4; r++) {
                a[r] = rp[(size_t)r * 64 + lane];
                c[r] = rp[(size_t)r * 64 + lane + 32];
            }
            float s[4];
#pragma unroll
            for (int r = 0; r < 4; r++) {
                s[r] = a[r].x * pa.x + a[r].y * pa.y + a[r].z * pa.z + a[r].w * pa.w
                     + c[r].x * pc.x + c[r].y * pc.y + c[r].z * pc.z + c[r].w * pc.w;
#pragma unroll
                for (int o = 16; o; o >>= 1) s[r] += __shfl_xor_sync(0xFFFFFFFFu, s[r], o);
            }
            if (lane < 4) g_dot[row0 + lane] = s[lane];
        }

        int graph = base / N;
        __threadfence();
        if (tid == 0) {
            int old = atomicAdd(&g_doneTiles[graph], 1);
            sm.s_flagdone = (old == tilesPerGraph - 1) ? 1 : 0;
        }
        __syncthreads();

        if (sm.s_flagdone) {
            // this block completed graph's dots: select + publish readiness
            select_graph(graph, N, K, D, out, sm);
            if (tid == 0) {
                __threadfence();
                atomicExch(&g_flag[graph], 1);
                // advance prefix-ready frontier
                int f = g_frontier;
                while (f < B && atomicAdd(&g_flag[f], 0) == 1) {
                    atomicCAS(&g_frontier, f, f + 1);
                    f = g_frontier;
                }
            }
            __syncthreads();
        }

        // opportunistic gather: claim only tickets provably below the ready
        // frontier (CAS-bounded -> never spins -> no deadlock in this phase)
        if (tid == 0) {
            int claimed = -1;
            int lim = atomicAdd(&g_frontier, 0) * SPLIT;
            int gt = atomicAdd(&g_gatherTicket, 0);
            while (gt < lim && gt < totalGatherTickets) {
                int prev = atomicCAS(&g_gatherTicket, gt, gt + 1);
                if (prev == gt) { claimed = gt; break; }
                gt = prev;
                lim = atomicAdd(&g_frontier, 0) * SPLIT;
            }
            sm.s_ticket = claimed;
        }
        __syncthreads();
        int gt = sm.s_ticket;
        __syncthreads();
        if (gt >= 0) {
            __threadfence();
            gather_item(gt / SPLIT, gt % SPLIT, K, D, logits, out, sm);
        }
    }

    // ---------- phase 2: drain remaining gather tickets (blocking claim) ----------
    while (true) {
        if (tid == 0) sm.s_ticket = atomicAdd(&g_gatherTicket, 1);
        __syncthreads();
        int t = sm.s_ticket;
        __syncthreads();
        if (t >= totalGatherTickets) break;
        int b = t / SPLIT;
        if (tid == 0) {
            // safe: all dot work is done or in flight on resident blocks,
            // so every select completes and sets its flag
            while (atomicAdd(&g_flag[b], 0) == 0) __nanosleep(100);
        }
        __syncthreads();
        __threadfence();
        gather_item(b, t % SPLIT, K, D, logits, out, sm);
    }
}

// ---------------- launcher ----------------
extern "C" void kernel_launch(void* const* d_in, const int* in_sizes, int n_in,
                              void* d_out, int out_size) {
    const float* logits = (const float*)d_in[0];
    const float* proj = (const float*)d_in[2];
    float* out = (float*)d_out;

    int D = in_sizes[2];                 // 256
    int T = in_sizes[1];                 // 262144
    int B = out_size / D;                // 64
    int N = T / B;                       // 4096
    int K = (int)ceil(0.2 * (double)N);  // 820

    // grid sized so ALL blocks are resident (persistent-kernel requirement)
    static int grid = 0;
    if (grid == 0) {
        int dev = 0, sms = 0, occ = 0;
        cudaGetDevice(&dev);
        cudaDeviceGetAttribute(&sms, cudaDevAttrMultiProcessorCount, dev);
        cudaOccupancyMaxActiveBlocksPerMultiprocessor(&occ, fused_kernel, 256, 0);
        if (occ < 1) occ = 1;
        grid = sms * occ;
        int maxTiles = T / TILE_ROWS;
        if (grid > maxTiles) grid = maxTiles;
    }

    init_kernel<<<1, 256>>>();
    fused_kernel<<<grid, 256>>>(logits, proj, out, T, N, K, D, B);
}

// round 5
// speedup vs baseline: 5.0072x; 5.0072x over previous
#include <cuda_runtime.h>
#include <math.h>

// ---------------- scratch (no allocs allowed) ----------------
#define MAX_T (64 * 4096)
#define MAX_B 64
#define MAX_K 1024
__device__ float g_dot[MAX_T];          // per-node dot(logits, proj)
__device__ int   g_idx[MAX_B * MAX_K];  // selected global node indices per graph

// ---------------- kernel 1: per-row dot product ----------------
// One warp per 4 rows; all 8 float4 loads issued before reduction (MLP=8).
__global__ void dot_kernel(const float* __restrict__ logits,
                           const float* __restrict__ proj,
                           float* __restrict__ dots,
                           int rowBase, int rowEnd) {
    __shared__ float4 pS[64];
    int tid = threadIdx.x;
    if (tid < 64) pS[tid] = reinterpret_cast<const float4*>(proj)[tid];
    __syncthreads();

    int warp = tid >> 5, lane = tid & 31;
    int row0 = rowBase + (blockIdx.x * 8 + warp) * 4;
    if (row0 >= rowEnd) return;

    const float4* rp = reinterpret_cast<const float4*>(logits) + (size_t)row0 * 64;

    float4 a[4], c[4];
#pragma unroll
    for (int r = 0; r < 4; r++) {
        a[r] = rp[(size_t)r * 64 + lane];
        c[r] = rp[(size_t)r * 64 + lane + 32];
    }
    float4 pa = pS[lane];
    float4 pc = pS[lane + 32];

    float s[4];
#pragma unroll
    for (int r = 0; r < 4; r++) {
        s[r] = a[r].x * pa.x + a[r].y * pa.y + a[r].z * pa.z + a[r].w * pa.w
             + c[r].x * pc.x + c[r].y * pc.y + c[r].z * pc.z + c[r].w * pc.w;
#pragma unroll
        for (int o = 16; o; o >>= 1) s[r] += __shfl_xor_sync(0xFFFFFFFFu, s[r], o);
    }
    if (lane < 4) dots[row0 + lane] = s[lane];
}

// ---------------- kernel 2: per-graph radix select + compaction ----------------
// One block (512 threads) per graph (graph id = bBase + blockIdx.x).
// 4x 8-bit MSB-first radix passes; bin choice via two-level warp suffix-scan.
// Also zeroes this graph's output row.
__global__ void __launch_bounds__(512)
select_kernel(const float* __restrict__ dots,
              int* __restrict__ idxList,
              float* __restrict__ out,
              int N, int K, int D, int bBase) {
    __shared__ unsigned keys[4096];
    __shared__ unsigned hist[256];
    __shared__ unsigned warpTot[8];   // per-warp totals for the 2-level scan
    __shared__ unsigned s_chosen;
    __shared__ unsigned s_need;
    __shared__ int cntGT, cntEQ;

    int b = bBase + blockIdx.x, tid = threadIdx.x;
    int lane = tid & 31, warp = tid >> 5;
    const float* d = dots + (size_t)b * N;

    for (int i = tid; i < D; i += blockDim.x) out[(size_t)b * D + i] = 0.0f;

    for (int i = tid; i < N; i += blockDim.x) {
        unsigned u = __float_as_uint(d[i]);
        u ^= (u >> 31) ? 0xFFFFFFFFu : 0x80000000u;  // order-preserving
        keys[i] = u;
    }
    if (tid == 0) s_need = (unsigned)K;
    __syncthreads();

    unsigned prefix = 0, mask = 0;
#pragma unroll
    for (int pass = 0; pass < 4; pass++) {
        int shift = 24 - 8 * pass;
        unsigned need = s_need;
        if (tid < 256) hist[tid] = 0;
        __syncthreads();
        for (int i = tid; i < N; i += blockDim.x) {
            unsigned kk = keys[i];
            if ((kk & mask) == prefix)
                atomicAdd(&hist[(kk >> shift) & 0xFFu], 1u);
        }
        __syncthreads();
        // two-level suffix scan over 256 bins: warps 0..7 own bins [w*32, w*32+32)
        if (warp < 8) {
            unsigned v = hist[warp * 32 + lane];
            // inclusive suffix scan within warp (descending bins)
            unsigned sum = v;
#pragma unroll
            for (int o = 1; o < 32; o <<= 1) {
                unsigned t = __shfl_down_sync(0xFFFFFFFFu, sum, o);
                if (lane + o < 32) sum += t;
            }
            if (lane == 0) warpTot[warp] = sum;   // total of this warp's 32 bins
            __syncwarp();
            hist[warp * 32 + lane] = sum;          // intra-warp suffix (no higher warps yet)
        }
        __syncthreads();
        if (tid < 256) {
            // add totals of all higher-bin warps
            unsigned add = 0;
            int myw = tid >> 5;
#pragma unroll
            for (int w = 0; w < 8; w++)
                if (w > myw) add += warpTot[w];
            unsigned st = hist[tid] + add;
            unsigned sn;  // suffix starting at bin tid+1
            if ((tid & 31) == 31) {
                sn = add;
            } else {
                sn = st - 0;  // placeholder; recompute below from neighbor
                sn = hist[tid + 1] + add;
            }
            if (tid == 255) sn = 0;
            if (st >= need && sn < need) {   // unique largest bin with suffix >= need
                s_chosen = (unsigned)tid;
                s_need = need - sn;
            }
        }
        __syncthreads();
        prefix |= s_chosen << shift;
        mask   |= 0xFFu << shift;
        __syncthreads();
    }

    unsigned thr = prefix;  // exact key of the k-th largest
    if (tid == 0) {
        cntGT = 0;
        cntEQ = K - (int)s_need;  // strictly-greater count; ties fill [G, K)
    }
    __syncthreads();

    int* lst = idxList + (size_t)b * K;
    for (int i = tid; i < N; i += blockDim.x) {
        unsigned kk = keys[i];
        if (kk > thr) {
            int p = atomicAdd(&cntGT, 1);
            lst[p] = b * N + i;
        } else if (kk == thr) {
            int p = atomicAdd(&cntEQ, 1);
            if (p < K) lst[p] = b * N + i;
        }
    }
}

// ---------------- kernel 3: gather + segment sum ----------------
// Indices staged in smem first -> all row loads independent (high MLP).
__global__ void gather_sum_kernel(const float* __restrict__ logits,
                                  const int* __restrict__ idxList,
                                  float* __restrict__ out,
                                  int K, int D, int SPLIT, int bBase) {
    __shared__ int sidx[64];
    int b = bBase + blockIdx.x / SPLIT;
    int s = blockIdx.x % SPLIT;
    int tid = threadIdx.x;

    int per = (K + SPLIT - 1) / SPLIT;
    int r0 = s * per;
    int r1 = min(K, r0 + per);
    int cnt = r1 - r0;
    if (cnt <= 0) return;

    if (tid < cnt) sidx[tid] = idxList[(size_t)b * K + r0 + tid];
    __syncthreads();

    float acc = 0.0f;
    int r = 0;
#pragma unroll 1
    for (; r + 8 <= cnt; r += 8) {
        float v0 = logits[(size_t)sidx[r + 0] * D + tid];
        float v1 = logits[(size_t)sidx[r + 1] * D + tid];
        float v2 = logits[(size_t)sidx[r + 2] * D + tid];
        float v3 = logits[(size_t)sidx[r + 3] * D + tid];
        float v4 = logits[(size_t)sidx[r + 4] * D + tid];
        float v5 = logits[(size_t)sidx[r + 5] * D + tid];
        float v6 = logits[(size_t)sidx[r + 6] * D + tid];
        float v7 = logits[(size_t)sidx[r + 7] * D + tid];
        acc += ((v0 + v1) + (v2 + v3)) + ((v4 + v5) + (v6 + v7));
    }
    for (; r < cnt; r++) acc += logits[(size_t)sidx[r] * D + tid];

    atomicAdd(&out[b * D + tid], acc);
}

// ---------------- launcher: 2-chunk pipelined DAG ----------------
extern "C" void kernel_launch(void* const* d_in, const int* in_sizes, int n_in,
                              void* d_out, int out_size) {
    const float* logits = (const float*)d_in[0];
    const float* proj = (const float*)d_in[2];
    float* out = (float*)d_out;

    int D = in_sizes[2];                 // 256
    int T = in_sizes[1];                 // 262144
    int B = out_size / D;                // 64
    int N = T / B;                       // 4096
    int K = (int)ceil(0.2 * (double)N);  // 820

    float* dots;
    int* idxList;
    cudaGetSymbolAddress((void**)&dots, g_dot);
    cudaGetSymbolAddress((void**)&idxList, g_idx);

    // Lazily created side stream/events (first call is the eager correctness
    // call, so creation never happens during graph capture).
    static cudaStream_t sSide = nullptr;
    static cudaEvent_t evDot0, evSideDone;
    if (sSide == nullptr) {
        cudaStreamCreateWithFlags(&sSide, cudaStreamNonBlocking);
        cudaEventCreateWithFlags(&evDot0, cudaEventDisableTiming);
        cudaEventCreateWithFlags(&evSideDone, cudaEventDisableTiming);
    }

    const int CH = (B % 2 == 0) ? 2 : 1;
    const int GB = B / CH;               // graphs per chunk
    const int rowsPerChunk = GB * N;
    const int SPLIT = 32;

    // chunk 0 dots on main stream
    dot_kernel<<<(rowsPerChunk + 31) / 32, 256>>>(logits, proj, dots,
                                                  0, rowsPerChunk);
    cudaEventRecord(evDot0, 0);

    // chunk 1 dots on main stream (overlaps side-stream select/gather of chunk 0)
    if (CH == 2) {
        dot_kernel<<<(rowsPerChunk + 31) / 32, 256>>>(logits, proj, dots,
                                                      rowsPerChunk, 2 * rowsPerChunk);
    }

    // side stream: select + gather for chunk 0, overlapped with chunk-1 dots
    cudaStreamWaitEvent(sSide, evDot0, 0);
    select_kernel<<<GB, 512, 0, sSide>>>(dots, idxList, out, N, K, D, 0);
    gather_sum_kernel<<<GB * SPLIT, D, 0, sSide>>>(logits, idxList, out,
                                                   K, D, SPLIT, 0);
    cudaEventRecord(evSideDone, sSide);

    // main stream tail: select + gather for chunk 1
    if (CH == 2) {
        select_kernel<<<GB, 512>>>(dots, idxList, out, N, K, D, GB);
        gather_sum_kernel<<<GB * SPLIT, D>>>(logits, idxList, out,
                                             K, D, SPLIT, GB);
    }

    // join side stream back into the main stream
    cudaStreamWaitEvent(0, evSideDone, 0);
}